// round 5
// baseline (speedup 1.0000x reference)
#include <cuda_runtime.h>
#include <cuda_bf16.h>

#define NS    150
#define BATCH 32
#define DIN   1024
#define DH    512
#define DOUT  256

#define L1_TILES (NS * (DH / 128))     // 600
#define L2_TILES (NS * (DOUT / 128))   // 300
#define TOT_TILES (L1_TILES + L2_TILES)

// -------------------- scratch (no cudaMalloc allowed) --------------------
__device__ float g_sW1[DH * DIN];
__device__ float g_sW2[DOUT * DH];
__device__ float g_H[NS * BATCH * DH];
__device__ int   g_q;
__device__ int   g_done1[NS];

// -------------------- threefry2x32 (JAX-exact, frozen) --------------------
__device__ __forceinline__ void tf2x32(unsigned k0, unsigned k1,
                                       unsigned x0, unsigned x1,
                                       unsigned& o0, unsigned& o1)
{
    const unsigned ks2 = k0 ^ k1 ^ 0x1BD11BDAu;
    x0 += k0; x1 += k1;
#define TF_RND(r) { x0 += x1; x1 = __funnelshift_l(x1, x1, (r)); x1 ^= x0; }
    TF_RND(13) TF_RND(15) TF_RND(26) TF_RND(6)   x0 += k1;  x1 += ks2 + 1u;
    TF_RND(17) TF_RND(29) TF_RND(16) TF_RND(24)  x0 += ks2; x1 += k0  + 2u;
    TF_RND(13) TF_RND(15) TF_RND(26) TF_RND(6)   x0 += k0;  x1 += k1  + 3u;
    TF_RND(17) TF_RND(29) TF_RND(16) TF_RND(24)  x0 += k1;  x1 += ks2 + 4u;
    TF_RND(13) TF_RND(15) TF_RND(26) TF_RND(6)   x0 += ks2; x1 += k0  + 5u;
#undef TF_RND
    o0 = x0; o1 = x1;
}

__device__ __forceinline__ float bits_to_normal(unsigned bits)
{
    float f = __uint_as_float((bits >> 9) | 0x3f800000u) - 1.0f;
    float x = fmaf(f, 2.0f, -0.99999994f);

    float w = -__logf(fmaf(-x, x, 1.0f));
    float p;
    if (w < 5.0f) {
        w -= 2.5f;
        p = 2.81022636e-08f;
        p = fmaf(p, w, 3.43273939e-07f);
        p = fmaf(p, w, -3.5233877e-06f);
        p = fmaf(p, w, -4.39150654e-06f);
        p = fmaf(p, w, 0.00021858087f);
        p = fmaf(p, w, -0.00125372503f);
        p = fmaf(p, w, -0.00417768164f);
        p = fmaf(p, w, 0.246640727f);
        p = fmaf(p, w, 1.50140941f);
    } else {
        w = sqrtf(w) - 3.0f;
        p = -0.000200214257f;
        p = fmaf(p, w, 0.000100950558f);
        p = fmaf(p, w, 0.00134934322f);
        p = fmaf(p, w, -0.00367342844f);
        p = fmaf(p, w, 0.00573950773f);
        p = fmaf(p, w, -0.0076224613f);
        p = fmaf(p, w, 0.00943887047f);
        p = fmaf(p, w, 1.00167406f);
        p = fmaf(p, w, 2.83297682f);
    }
    return 1.41421356237f * (p * x);
}

__device__ __forceinline__ float tf_normal(unsigned k0, unsigned k1, unsigned e)
{
    unsigned o0, o1;
    tf2x32(k0, k1, 0u, e, o0, o1);
    return bits_to_normal(o0 ^ o1);
}

// 4 interleaved threefry chains -> ILP 4 on the ALU dependency chain.
__device__ __forceinline__ void tf_normal4(unsigned k0, unsigned k1, unsigned e,
                                           float r[4])
{
    const unsigned ks2 = k0 ^ k1 ^ 0x1BD11BDAu;
    unsigned a[4], b[4];
#pragma unroll
    for (int i = 0; i < 4; i++) { a[i] = k0; b[i] = (e + (unsigned)i) + k1; }

#define TF_R4(rr) _Pragma("unroll") \
    for (int i = 0; i < 4; i++) { a[i] += b[i]; b[i] = __funnelshift_l(b[i], b[i], (rr)); b[i] ^= a[i]; }
#define TF_INJ4(ka, kb, g) _Pragma("unroll") \
    for (int i = 0; i < 4; i++) { a[i] += (ka); b[i] += (kb) + (g); }

    TF_R4(13) TF_R4(15) TF_R4(26) TF_R4(6)   TF_INJ4(k1,  ks2, 1u)
    TF_R4(17) TF_R4(29) TF_R4(16) TF_R4(24)  TF_INJ4(ks2, k0,  2u)
    TF_R4(13) TF_R4(15) TF_R4(26) TF_R4(6)   TF_INJ4(k0,  k1,  3u)
    TF_R4(17) TF_R4(29) TF_R4(16) TF_R4(24)  TF_INJ4(k1,  ks2, 4u)
    TF_R4(13) TF_R4(15) TF_R4(26) TF_R4(6)   TF_INJ4(ks2, k0,  5u)
#undef TF_R4
#undef TF_INJ4

#pragma unroll
    for (int i = 0; i < 4; i++) r[i] = bits_to_normal(a[i] ^ b[i]);
}

// -------------------- packed f32x2 helpers --------------------
__device__ __forceinline__ unsigned long long ffma2(unsigned long long a,
                                                    unsigned long long b,
                                                    unsigned long long c)
{
    unsigned long long d;
    asm("fma.rn.f32x2 %0, %1, %2, %3;" : "=l"(d) : "l"(a), "l"(b), "l"(c));
    return d;
}
__device__ __forceinline__ float2 unpack2(unsigned long long d)
{
    unsigned lo, hi;
    asm("mov.b64 {%0, %1}, %2;" : "=r"(lo), "=r"(hi) : "l"(d));
    return make_float2(__uint_as_float(lo), __uint_as_float(hi));
}

// -------------------- prep: exp(v_W) + reset queue/counters --------------------
__global__ __launch_bounds__(256) void prep_kernel(const float* __restrict__ vW1,
                                                   const float* __restrict__ vW2)
{
    int i = blockIdx.x * 256 + threadIdx.x;
    if (i < DH * DIN)  g_sW1[i] = expf(vW1[i]);
    if (i < DOUT * DH) g_sW2[i] = expf(vW2[i]);
    if (i < NS)        g_done1[i] = 0;
    if (i == NS)       g_q = 0;
}

// -------------------- one fused 128-wide tile --------------------
// Out[n][b][c0..c0+127] = act(bias + sum_k X[b][k] * (mu[c][k] + eps*s[c][k]))
// 128 threads, thread = 4 b x 8 c (4 f32x2 accumulator pairs), x duplicated.
template<int K, int N, bool RELU>
__device__ __forceinline__ void tile128(
    int n, int c0,
    const float* __restrict__ Xn,
    const float* __restrict__ mu, const float* __restrict__ s,
    const float* __restrict__ mub, const float* __restrict__ vb,
    float* __restrict__ Out,
    unsigned wk0, unsigned wk1, unsigned bk0, unsigned bk1,
    float2 (&xs)[32][33], float (&ws)[32][130], float (&bs)[128])
{
    const int tid = threadIdx.x;
    const int b0 = (tid & 7) * 4;
    const int h0 = (tid >> 3) * 8;

    const int gr  = tid;                 // c-row this thread generates (whole row)

    // per-tile sampled bias: e = n*N + c
    {
        int c = c0 + tid;
        float eps = tf_normal(bk0, bk1, (unsigned)(n * N + c));
        bs[tid] = fmaf(eps, expf(vb[c]), mub[c]);
    }

    unsigned long long acc[4][4];
#pragma unroll
    for (int i = 0; i < 4; i++)
#pragma unroll
        for (int j = 0; j < 4; j++) acc[i][j] = 0ull;

    const unsigned erow = (unsigned)(n * N + c0 + gr) * (unsigned)K;
    const float* muRow = mu + (long long)(c0 + gr) * K;
    const float* sRow  = s  + (long long)(c0 + gr) * K;

    for (int k0 = 0; k0 < K; k0 += 32) {
        // ---- x tile: duplicated float2 so FMA loop is pure LDS.64 ----
        {
            int idx = tid;
#pragma unroll
            for (int t = 0; t < 2; t++) {
                int r = idx >> 3, c4 = idx & 7;
                float4 xv = *reinterpret_cast<const float4*>(Xn + r * K + k0 + c4 * 4);
                xs[c4 * 4 + 0][r] = make_float2(xv.x, xv.x);
                xs[c4 * 4 + 1][r] = make_float2(xv.y, xv.y);
                xs[c4 * 4 + 2][r] = make_float2(xv.z, xv.z);
                xs[c4 * 4 + 3][r] = make_float2(xv.w, xv.w);
                idx += 128;
            }
        }
        // ---- generate 128c x 32k weight tile: thread = full c-row, 8 quads ----
#pragma unroll
        for (int q = 0; q < 8; q++) {
            int kk = q * 4;
            float r4[4];
            tf_normal4(wk0, wk1, erow + (unsigned)(k0 + kk), r4);
            float4 m  = *reinterpret_cast<const float4*>(muRow + k0 + kk);
            float4 sv = *reinterpret_cast<const float4*>(sRow  + k0 + kk);
            ws[kk + 0][gr] = fmaf(r4[0], sv.x, m.x);
            ws[kk + 1][gr] = fmaf(r4[1], sv.y, m.y);
            ws[kk + 2][gr] = fmaf(r4[2], sv.z, m.z);
            ws[kk + 3][gr] = fmaf(r4[3], sv.w, m.w);
        }
        __syncthreads();

        // ---- packed-f32x2 FMA: 8 LDS.64 -> 32 FFMA2 ----
#pragma unroll 4
        for (int kk = 0; kk < 32; kk++) {
            unsigned long long xd[4], wd[4];
#pragma unroll
            for (int i = 0; i < 4; i++)
                xd[i] = *reinterpret_cast<const unsigned long long*>(&xs[kk][b0 + i]);
#pragma unroll
            for (int j = 0; j < 4; j++)
                wd[j] = *reinterpret_cast<const unsigned long long*>(&ws[kk][h0 + 2 * j]);
#pragma unroll
            for (int i = 0; i < 4; i++)
#pragma unroll
                for (int j = 0; j < 4; j++)
                    acc[i][j] = ffma2(xd[i], wd[j], acc[i][j]);
        }
        __syncthreads();
    }

#pragma unroll
    for (int j = 0; j < 4; j++) {
        float bj0 = bs[h0 + 2 * j];
        float bj1 = bs[h0 + 2 * j + 1];
#pragma unroll
        for (int i = 0; i < 4; i++) {
            float2 v = unpack2(acc[i][j]);
            v.x += bj0; v.y += bj1;
            if (RELU) { v.x = fmaxf(v.x, 0.0f); v.y = fmaxf(v.y, 0.0f); }
            *reinterpret_cast<float2*>(
                Out + ((long long)n * BATCH + (b0 + i)) * N + c0 + h0 + 2 * j) = v;
        }
    }
}

// -------------------- persistent worker: both layers via work queue --------------------
__global__ __launch_bounds__(128, 5) void persist_kernel(
    const float* __restrict__ x,
    const float* __restrict__ muW1, const float* __restrict__ mub1,
    const float* __restrict__ vb1,
    const float* __restrict__ muW2, const float* __restrict__ mub2,
    const float* __restrict__ vb2,
    float* __restrict__ out,
    unsigned k10, unsigned k11, unsigned k20, unsigned k21,
    unsigned k30, unsigned k31, unsigned k40, unsigned k41)
{
    __shared__ float2 xs[32][33];
    __shared__ float  ws[32][130];
    __shared__ float  bs[128];
    __shared__ int    s_item;

    for (;;) {
        if (threadIdx.x == 0) s_item = atomicAdd(&g_q, 1);
        __syncthreads();
        const int item = s_item;
        if (item >= TOT_TILES) break;

        if (item < L1_TILES) {
            const int n = item >> 2;                 // 4 tiles per sample
            const int c0 = (item & 3) * 128;
            tile128<DIN, DH, true>(n, c0, x, muW1, g_sW1, mub1, vb1, g_H,
                                   k10, k11, k20, k21, xs, ws, bs);
            __syncthreads();
            if (threadIdx.x == 0) {
                __threadfence();                     // release H writes
                atomicAdd(&g_done1[n], 1);
            }
        } else {
            const int i2 = item - L1_TILES;
            const int n = i2 >> 1;                   // 2 tiles per sample
            const int c0 = (i2 & 1) * 128;
            if (threadIdx.x == 0) {
                while (*(volatile int*)&g_done1[n] < 4) __nanosleep(64);
                __threadfence();                     // acquire H writes
            }
            __syncthreads();
            tile128<DH, DOUT, false>(n, c0, g_H + (long long)n * BATCH * DH,
                                     muW2, g_sW2, mub2, vb2, out,
                                     k30, k31, k40, k41, xs, ws, bs);
        }
        __syncthreads();                             // protect smem reuse
    }
}

// -------------------- host-side threefry for subkey derivation --------------------
static inline unsigned h_rotl(unsigned x, int r) { return (x << r) | (x >> (32 - r)); }
static void h_tf2x32(unsigned k0, unsigned k1, unsigned x0, unsigned x1,
                     unsigned& o0, unsigned& o1)
{
    const unsigned ks2 = k0 ^ k1 ^ 0x1BD11BDAu;
    x0 += k0; x1 += k1;
    static const int R[2][4] = {{13, 15, 26, 6}, {17, 29, 16, 24}};
    const unsigned ks[3] = {k0, k1, ks2};
    for (int g = 0; g < 5; g++) {
        for (int r = 0; r < 4; r++) {
            x0 += x1; x1 = h_rotl(x1, R[g & 1][r]); x1 ^= x0;
        }
        x0 += ks[(g + 1) % 3];
        x1 += ks[(g + 2) % 3] + (unsigned)(g + 1);
    }
    o0 = x0; o1 = x1;
}

extern "C" void kernel_launch(void* const* d_in, const int* in_sizes, int n_in,
                              void* d_out, int out_size)
{
    const float* x    = (const float*)d_in[0];
    const float* muW1 = (const float*)d_in[1];
    const float* mub1 = (const float*)d_in[2];
    const float* muW2 = (const float*)d_in[3];
    const float* mub2 = (const float*)d_in[4];
    const float* vW1  = (const float*)d_in[5];
    const float* vb1  = (const float*)d_in[6];
    const float* vW2  = (const float*)d_in[7];
    const float* vb2  = (const float*)d_in[8];
    float* out = (float*)d_out;

    unsigned keys[4][2];
    for (unsigned i = 0; i < 4; i++)
        h_tf2x32(0u, 42u, 0u, i, keys[i][0], keys[i][1]);

    static int nblocks = 0;
    if (nblocks == 0) {
        int sms = 148;
        cudaDeviceGetAttribute(&sms, cudaDevAttrMultiProcessorCount, 0);
        nblocks = sms * 5;
        if (nblocks > TOT_TILES) nblocks = TOT_TILES;
    }

    prep_kernel<<<(DH * DIN + 255) / 256, 256>>>(vW1, vW2);

    persist_kernel<<<nblocks, 128>>>(
        x, muW1, mub1, vb1, muW2, mub2, vb2, out,
        keys[0][0], keys[0][1], keys[1][0], keys[1][1],
        keys[2][0], keys[2][1], keys[3][0], keys[3][1]);
}

// round 6
// speedup vs baseline: 1.2011x; 1.2011x over previous
#include <cuda_runtime.h>
#include <cuda_bf16.h>

#define NS    150
#define BATCH 32
#define DIN   1024
#define DH    512
#define DOUT  256

#define L1_TILES (NS * (DH / 128))     // 600
#define L2_TILES (NS * (DOUT / 128))   // 300
#define TOT_TILES (L1_TILES + L2_TILES)

// -------------------- scratch (no cudaMalloc allowed) --------------------
__device__ float g_sW1[DH * DIN];
__device__ float g_sW2[DOUT * DH];
__device__ float g_H[NS * BATCH * DH];
__device__ int   g_q;
__device__ int   g_done1[NS];

// -------------------- threefry2x32 (JAX-exact, frozen) --------------------
__device__ __forceinline__ void tf2x32(unsigned k0, unsigned k1,
                                       unsigned x0, unsigned x1,
                                       unsigned& o0, unsigned& o1)
{
    const unsigned ks2 = k0 ^ k1 ^ 0x1BD11BDAu;
    x0 += k0; x1 += k1;
#define TF_RND(r) { x0 += x1; x1 = __funnelshift_l(x1, x1, (r)); x1 ^= x0; }
    TF_RND(13) TF_RND(15) TF_RND(26) TF_RND(6)   x0 += k1;  x1 += ks2 + 1u;
    TF_RND(17) TF_RND(29) TF_RND(16) TF_RND(24)  x0 += ks2; x1 += k0  + 2u;
    TF_RND(13) TF_RND(15) TF_RND(26) TF_RND(6)   x0 += k0;  x1 += k1  + 3u;
    TF_RND(17) TF_RND(29) TF_RND(16) TF_RND(24)  x0 += k1;  x1 += ks2 + 4u;
    TF_RND(13) TF_RND(15) TF_RND(26) TF_RND(6)   x0 += ks2; x1 += k0  + 5u;
#undef TF_RND
    o0 = x0; o1 = x1;
}

__device__ __forceinline__ float bits_to_normal(unsigned bits)
{
    float f = __uint_as_float((bits >> 9) | 0x3f800000u) - 1.0f;
    float x = fmaf(f, 2.0f, -0.99999994f);

    float w = -__logf(fmaf(-x, x, 1.0f));
    float p;
    if (w < 5.0f) {
        w -= 2.5f;
        p = 2.81022636e-08f;
        p = fmaf(p, w, 3.43273939e-07f);
        p = fmaf(p, w, -3.5233877e-06f);
        p = fmaf(p, w, -4.39150654e-06f);
        p = fmaf(p, w, 0.00021858087f);
        p = fmaf(p, w, -0.00125372503f);
        p = fmaf(p, w, -0.00417768164f);
        p = fmaf(p, w, 0.246640727f);
        p = fmaf(p, w, 1.50140941f);
    } else {
        w = sqrtf(w) - 3.0f;
        p = -0.000200214257f;
        p = fmaf(p, w, 0.000100950558f);
        p = fmaf(p, w, 0.00134934322f);
        p = fmaf(p, w, -0.00367342844f);
        p = fmaf(p, w, 0.00573950773f);
        p = fmaf(p, w, -0.0076224613f);
        p = fmaf(p, w, 0.00943887047f);
        p = fmaf(p, w, 1.00167406f);
        p = fmaf(p, w, 2.83297682f);
    }
    return 1.41421356237f * (p * x);
}

__device__ __forceinline__ float tf_normal(unsigned k0, unsigned k1, unsigned e)
{
    unsigned o0, o1;
    tf2x32(k0, k1, 0u, e, o0, o1);
    return bits_to_normal(o0 ^ o1);
}

// 4 interleaved threefry chains -> ILP 4 on the ALU dependency chain.
__device__ __forceinline__ void tf_normal4(unsigned k0, unsigned k1, unsigned e,
                                           float r[4])
{
    const unsigned ks2 = k0 ^ k1 ^ 0x1BD11BDAu;
    unsigned a[4], b[4];
#pragma unroll
    for (int i = 0; i < 4; i++) { a[i] = k0; b[i] = (e + (unsigned)i) + k1; }

#define TF_R4(rr) _Pragma("unroll") \
    for (int i = 0; i < 4; i++) { a[i] += b[i]; b[i] = __funnelshift_l(b[i], b[i], (rr)); b[i] ^= a[i]; }
#define TF_INJ4(ka, kb, g) _Pragma("unroll") \
    for (int i = 0; i < 4; i++) { a[i] += (ka); b[i] += (kb) + (g); }

    TF_R4(13) TF_R4(15) TF_R4(26) TF_R4(6)   TF_INJ4(k1,  ks2, 1u)
    TF_R4(17) TF_R4(29) TF_R4(16) TF_R4(24)  TF_INJ4(ks2, k0,  2u)
    TF_R4(13) TF_R4(15) TF_R4(26) TF_R4(6)   TF_INJ4(k0,  k1,  3u)
    TF_R4(17) TF_R4(29) TF_R4(16) TF_R4(24)  TF_INJ4(k1,  ks2, 4u)
    TF_R4(13) TF_R4(15) TF_R4(26) TF_R4(6)   TF_INJ4(ks2, k0,  5u)
#undef TF_R4
#undef TF_INJ4

#pragma unroll
    for (int i = 0; i < 4; i++) r[i] = bits_to_normal(a[i] ^ b[i]);
}

// -------------------- packed f32x2 helpers --------------------
__device__ __forceinline__ unsigned long long ffma2(unsigned long long a,
                                                    unsigned long long b,
                                                    unsigned long long c)
{
    unsigned long long d;
    asm("fma.rn.f32x2 %0, %1, %2, %3;" : "=l"(d) : "l"(a), "l"(b), "l"(c));
    return d;
}
__device__ __forceinline__ float2 unpack2(unsigned long long d)
{
    unsigned lo, hi;
    asm("mov.b64 {%0, %1}, %2;" : "=r"(lo), "=r"(hi) : "l"(d));
    return make_float2(__uint_as_float(lo), __uint_as_float(hi));
}

// -------------------- prep: exp(v_W) + reset queue/counters --------------------
__global__ __launch_bounds__(256) void prep_kernel(const float* __restrict__ vW1,
                                                   const float* __restrict__ vW2)
{
    int i = blockIdx.x * 256 + threadIdx.x;
    if (i < DH * DIN)  g_sW1[i] = expf(vW1[i]);
    if (i < DOUT * DH) g_sW2[i] = expf(vW2[i]);
    if (i < NS)        g_done1[i] = 0;
    if (i == NS)       g_q = 0;
}

// -------------------- one fused 128-wide tile --------------------
// Out[n][b][c0..c0+127] = act(bias + sum_k X[b][k] * (mu[c][k] + eps*s[c][k]))
// 128 threads, thread = 4 b x 8 c (4 f32x2 accumulator pairs), x duplicated.
template<int K, int N, bool RELU>
__device__ __forceinline__ void tile128(
    int n, int c0,
    const float* __restrict__ Xn,
    const float* __restrict__ mu, const float* __restrict__ s,
    const float* __restrict__ mub, const float* __restrict__ vb,
    float* __restrict__ Out,
    unsigned wk0, unsigned wk1, unsigned bk0, unsigned bk1,
    float2 (&xs)[32][33], float (&ws)[32][130], float (&bs)[128])
{
    const int tid = threadIdx.x;
    const int b0 = (tid & 7) * 4;
    const int h0 = (tid >> 3) * 8;

    const int gr = tid;                  // c-row this thread generates

    // per-tile sampled bias: e = n*N + c
    {
        int c = c0 + tid;
        float eps = tf_normal(bk0, bk1, (unsigned)(n * N + c));
        bs[tid] = fmaf(eps, expf(vb[c]), mub[c]);
    }

    unsigned long long acc[4][4];
#pragma unroll
    for (int i = 0; i < 4; i++)
#pragma unroll
        for (int j = 0; j < 4; j++) acc[i][j] = 0ull;

    const unsigned erow = (unsigned)(n * N + c0 + gr) * (unsigned)K;
    const float* muRow = mu + (long long)(c0 + gr) * K;
    const float* sRow  = s  + (long long)(c0 + gr) * K;

    for (int k0 = 0; k0 < K; k0 += 32) {
        // ---- x tile: duplicated float2 so FMA loop is pure LDS.64 ----
        {
            int idx = tid;
#pragma unroll
            for (int t = 0; t < 2; t++) {
                int r = idx >> 3, c4 = idx & 7;
                float4 xv = *reinterpret_cast<const float4*>(Xn + r * K + k0 + c4 * 4);
                xs[c4 * 4 + 0][r] = make_float2(xv.x, xv.x);
                xs[c4 * 4 + 1][r] = make_float2(xv.y, xv.y);
                xs[c4 * 4 + 2][r] = make_float2(xv.z, xv.z);
                xs[c4 * 4 + 3][r] = make_float2(xv.w, xv.w);
                idx += 128;
            }
        }
        // ---- generate 128c x 32k weight tile: thread = full c-row, 8 quads ----
#pragma unroll
        for (int q = 0; q < 8; q++) {
            int kk = q * 4;
            float r4[4];
            tf_normal4(wk0, wk1, erow + (unsigned)(k0 + kk), r4);
            float4 m  = *reinterpret_cast<const float4*>(muRow + k0 + kk);
            float4 sv = *reinterpret_cast<const float4*>(sRow  + k0 + kk);
            ws[kk + 0][gr] = fmaf(r4[0], sv.x, m.x);
            ws[kk + 1][gr] = fmaf(r4[1], sv.y, m.y);
            ws[kk + 2][gr] = fmaf(r4[2], sv.z, m.z);
            ws[kk + 3][gr] = fmaf(r4[3], sv.w, m.w);
        }
        __syncthreads();

        // ---- packed-f32x2 FMA: 8 LDS.64 -> 32 FFMA2 ----
#pragma unroll 4
        for (int kk = 0; kk < 32; kk++) {
            unsigned long long xd[4], wd[4];
#pragma unroll
            for (int i = 0; i < 4; i++)
                xd[i] = *reinterpret_cast<const unsigned long long*>(&xs[kk][b0 + i]);
#pragma unroll
            for (int j = 0; j < 4; j++)
                wd[j] = *reinterpret_cast<const unsigned long long*>(&ws[kk][h0 + 2 * j]);
#pragma unroll
            for (int i = 0; i < 4; i++)
#pragma unroll
                for (int j = 0; j < 4; j++)
                    acc[i][j] = ffma2(xd[i], wd[j], acc[i][j]);
        }
        __syncthreads();
    }

#pragma unroll
    for (int j = 0; j < 4; j++) {
        float bj0 = bs[h0 + 2 * j];
        float bj1 = bs[h0 + 2 * j + 1];
#pragma unroll
        for (int i = 0; i < 4; i++) {
            float2 v = unpack2(acc[i][j]);
            v.x += bj0; v.y += bj1;
            if (RELU) { v.x = fmaxf(v.x, 0.0f); v.y = fmaxf(v.y, 0.0f); }
            *reinterpret_cast<float2*>(
                Out + ((long long)n * BATCH + (b0 + i)) * N + c0 + h0 + 2 * j) = v;
        }
    }
}

// -------------------- persistent worker: both layers via work queue --------------------
// launch_bounds(128, 4): full 128-reg budget (tile128 needs ~112 — NO spills),
// 4 blocks/SM resident.
__global__ __launch_bounds__(128, 4) void persist_kernel(
    const float* __restrict__ x,
    const float* __restrict__ muW1, const float* __restrict__ mub1,
    const float* __restrict__ vb1,
    const float* __restrict__ muW2, const float* __restrict__ mub2,
    const float* __restrict__ vb2,
    float* __restrict__ out,
    unsigned k10, unsigned k11, unsigned k20, unsigned k21,
    unsigned k30, unsigned k31, unsigned k40, unsigned k41)
{
    __shared__ float2 xs[32][33];
    __shared__ float  ws[32][130];
    __shared__ float  bs[128];
    __shared__ int    s_item;

    for (;;) {
        if (threadIdx.x == 0) s_item = atomicAdd(&g_q, 1);
        __syncthreads();
        const int item = s_item;
        if (item >= TOT_TILES) break;

        if (item < L1_TILES) {
            const int n = item >> 2;                 // 4 tiles per sample
            const int c0 = (item & 3) * 128;
            tile128<DIN, DH, true>(n, c0, x, muW1, g_sW1, mub1, vb1, g_H,
                                   k10, k11, k20, k21, xs, ws, bs);
            __syncthreads();
            if (threadIdx.x == 0) {
                __threadfence();                     // release H writes
                atomicAdd(&g_done1[n], 1);
            }
        } else {
            const int i2 = item - L1_TILES;
            const int n = i2 >> 1;                   // 2 tiles per sample
            const int c0 = (i2 & 1) * 128;
            if (threadIdx.x == 0) {
                while (*(volatile int*)&g_done1[n] < 4) __nanosleep(64);
                __threadfence();                     // acquire H writes
            }
            __syncthreads();
            tile128<DH, DOUT, false>(n, c0, g_H + (long long)n * BATCH * DH,
                                     muW2, g_sW2, mub2, vb2, out,
                                     k30, k31, k40, k41, xs, ws, bs);
        }
        __syncthreads();                             // protect smem reuse
    }
}

// -------------------- host-side threefry for subkey derivation --------------------
static inline unsigned h_rotl(unsigned x, int r) { return (x << r) | (x >> (32 - r)); }
static void h_tf2x32(unsigned k0, unsigned k1, unsigned x0, unsigned x1,
                     unsigned& o0, unsigned& o1)
{
    const unsigned ks2 = k0 ^ k1 ^ 0x1BD11BDAu;
    x0 += k0; x1 += k1;
    static const int R[2][4] = {{13, 15, 26, 6}, {17, 29, 16, 24}};
    const unsigned ks[3] = {k0, k1, ks2};
    for (int g = 0; g < 5; g++) {
        for (int r = 0; r < 4; r++) {
            x0 += x1; x1 = h_rotl(x1, R[g & 1][r]); x1 ^= x0;
        }
        x0 += ks[(g + 1) % 3];
        x1 += ks[(g + 2) % 3] + (unsigned)(g + 1);
    }
    o0 = x0; o1 = x1;
}

extern "C" void kernel_launch(void* const* d_in, const int* in_sizes, int n_in,
                              void* d_out, int out_size)
{
    const float* x    = (const float*)d_in[0];
    const float* muW1 = (const float*)d_in[1];
    const float* mub1 = (const float*)d_in[2];
    const float* muW2 = (const float*)d_in[3];
    const float* mub2 = (const float*)d_in[4];
    const float* vW1  = (const float*)d_in[5];
    const float* vb1  = (const float*)d_in[6];
    const float* vW2  = (const float*)d_in[7];
    const float* vb2  = (const float*)d_in[8];
    float* out = (float*)d_out;

    unsigned keys[4][2];
    for (unsigned i = 0; i < 4; i++)
        h_tf2x32(0u, 42u, 0u, i, keys[i][0], keys[i][1]);

    static int nblocks = 0;
    if (nblocks == 0) {
        int sms = 148;
        cudaDeviceGetAttribute(&sms, cudaDevAttrMultiProcessorCount, 0);
        nblocks = sms * 4;                       // all resident, no reg spills
        if (nblocks > TOT_TILES) nblocks = TOT_TILES;
    }

    prep_kernel<<<(DH * DIN + 255) / 256, 256>>>(vW1, vW2);

    persist_kernel<<<nblocks, 128>>>(
        x, muW1, mub1, vb1, muW2, mub2, vb2, out,
        keys[0][0], keys[0][1], keys[1][0], keys[1][1],
        keys[2][0], keys[2][1], keys[3][0], keys[3][1]);
}

// round 7
// speedup vs baseline: 1.3038x; 1.0855x over previous
#include <cuda_runtime.h>
#include <cuda_bf16.h>

#define NS    150
#define BATCH 32
#define DIN   1024
#define DH    512
#define DOUT  256

// -------------------- scratch (no cudaMalloc allowed) --------------------
__device__ float g_sW1[DH * DIN];        // exp(v_W1), sample-invariant
__device__ float g_sW2[DOUT * DH];       // exp(v_W2)
__device__ float g_H[NS * BATCH * DH];   // hidden activations

// -------------------- threefry2x32 (JAX-exact, frozen) --------------------
__device__ __forceinline__ void tf2x32(unsigned k0, unsigned k1,
                                       unsigned x0, unsigned x1,
                                       unsigned& o0, unsigned& o1)
{
    const unsigned ks2 = k0 ^ k1 ^ 0x1BD11BDAu;
    x0 += k0; x1 += k1;
#define TF_RND(r) { x0 += x1; x1 = __funnelshift_l(x1, x1, (r)); x1 ^= x0; }
    TF_RND(13) TF_RND(15) TF_RND(26) TF_RND(6)   x0 += k1;  x1 += ks2 + 1u;
    TF_RND(17) TF_RND(29) TF_RND(16) TF_RND(24)  x0 += ks2; x1 += k0  + 2u;
    TF_RND(13) TF_RND(15) TF_RND(26) TF_RND(6)   x0 += k0;  x1 += k1  + 3u;
    TF_RND(17) TF_RND(29) TF_RND(16) TF_RND(24)  x0 += k1;  x1 += ks2 + 4u;
    TF_RND(13) TF_RND(15) TF_RND(26) TF_RND(6)   x0 += ks2; x1 += k0  + 5u;
#undef TF_RND
    o0 = x0; o1 = x1;
}

// bits -> uniform(lo,1) -> sqrt(2)*erfinv. sqrt(2) folded into coefficients.
__device__ __forceinline__ float bits_to_normal(unsigned bits)
{
    float f = __uint_as_float((bits >> 9) | 0x3f800000u) - 1.0f;
    float x = fmaf(f, 2.0f, -0.99999994f);

    float w = -__logf(fmaf(-x, x, 1.0f));
    float p;
    if (__builtin_expect(w < 5.0f, 1)) {
        w -= 2.5f;
        p = 3.9742706e-08f;
        p = fmaf(p, w, 4.8546428e-07f);
        p = fmaf(p, w, -4.9828470e-06f);
        p = fmaf(p, w, -6.2105274e-06f);
        p = fmaf(p, w, 3.0912157e-04f);
        p = fmaf(p, w, -1.7730353e-03f);
        p = fmaf(p, w, -5.9081528e-03f);
        p = fmaf(p, w, 3.4876418e-01f);
        p = fmaf(p, w, 2.1233185e+00f);
    } else {
        w = sqrtf(w) - 3.0f;
        p = -2.8314684e-04f;
        p = fmaf(p, w, 1.4276577e-04f);
        p = fmaf(p, w, 1.9082628e-03f);
        p = fmaf(p, w, -5.1950289e-03f);
        p = fmaf(p, w, 8.1169003e-03f);
        p = fmaf(p, w, -1.0779794e-02f);
        p = fmaf(p, w, 1.3348587e-02f);
        p = fmaf(p, w, 1.4165829e+00f);
        p = fmaf(p, w, 4.0064237e+00f);
    }
    return p * x;
}

__device__ __forceinline__ float tf_normal(unsigned k0, unsigned k1, unsigned e)
{
    unsigned o0, o1;
    tf2x32(k0, k1, 0u, e, o0, o1);
    return bits_to_normal(o0 ^ o1);
}

// 4 interleaved threefry chains -> ILP 4 on the ALU dependency chain.
__device__ __forceinline__ void tf_normal4(unsigned k0, unsigned k1, unsigned e,
                                           float r[4])
{
    const unsigned ks2 = k0 ^ k1 ^ 0x1BD11BDAu;
    unsigned a[4], b[4];
#pragma unroll
    for (int i = 0; i < 4; i++) { a[i] = k0; b[i] = (e + (unsigned)i) + k1; }

#define TF_R4(rr) _Pragma("unroll") \
    for (int i = 0; i < 4; i++) { a[i] += b[i]; b[i] = __funnelshift_l(b[i], b[i], (rr)); b[i] ^= a[i]; }
#define TF_INJ4(ka, kb, g) _Pragma("unroll") \
    for (int i = 0; i < 4; i++) { a[i] += (ka); b[i] += (kb) + (g); }

    TF_R4(13) TF_R4(15) TF_R4(26) TF_R4(6)   TF_INJ4(k1,  ks2, 1u)
    TF_R4(17) TF_R4(29) TF_R4(16) TF_R4(24)  TF_INJ4(ks2, k0,  2u)
    TF_R4(13) TF_R4(15) TF_R4(26) TF_R4(6)   TF_INJ4(k0,  k1,  3u)
    TF_R4(17) TF_R4(29) TF_R4(16) TF_R4(24)  TF_INJ4(k1,  ks2, 4u)
    TF_R4(13) TF_R4(15) TF_R4(26) TF_R4(6)   TF_INJ4(ks2, k0,  5u)
#undef TF_R4
#undef TF_INJ4

#pragma unroll
    for (int i = 0; i < 4; i++) r[i] = bits_to_normal(a[i] ^ b[i]);
}

// -------------------- packed f32x2 helpers --------------------
__device__ __forceinline__ unsigned long long ffma2(unsigned long long a,
                                                    unsigned long long b,
                                                    unsigned long long c)
{
    unsigned long long d;
    asm("fma.rn.f32x2 %0, %1, %2, %3;" : "=l"(d) : "l"(a), "l"(b), "l"(c));
    return d;
}
__device__ __forceinline__ float2 unpack2(unsigned long long d)
{
    unsigned lo, hi;
    asm("mov.b64 {%0, %1}, %2;" : "=r"(lo), "=r"(hi) : "l"(d));
    return make_float2(__uint_as_float(lo), __uint_as_float(hi));
}

// -------------------- exp(v_W) precompute (bit-identical expf) --------------------
__global__ __launch_bounds__(256) void prep_kernel(const float* __restrict__ vW1,
                                                   const float* __restrict__ vW2)
{
    int i = blockIdx.x * 256 + threadIdx.x;
    if (i < DH * DIN)  g_sW1[i] = expf(vW1[i]);
    if (i < DOUT * DH) g_sW2[i] = expf(vW2[i]);
}

// -------------------- fused sample-and-GEMM, 64-thread blocks --------------------
// block = (n, 64-wide c tile); thread tile = 4b x 8c (4x4 f32x2 accumulators).
// Identical per-thread LDS:FFMA2 economy to the proven 128-wide tile (2B/FFMA2),
// but 16x finer scheduling granularity (8 blocks/SM, 1184 slots).
template<int K, int N, bool RELU>
__global__ __launch_bounds__(64, 8) void fused_kernel(
    const float* __restrict__ X, long long xStride,
    const float* __restrict__ mu, const float* __restrict__ s,
    const float* __restrict__ mub, const float* __restrict__ vb,
    float* __restrict__ Out,
    unsigned wk0, unsigned wk1, unsigned bk0, unsigned bk1)
{
    const int n  = blockIdx.x;
    const int c0 = blockIdx.y * 64;
    const float* Xn = X + (long long)n * xStride;

    __shared__ float2 xs[32][33];   // [k][b] duplicated -> pure LDS.64 in FMA loop
    __shared__ float  ws[32][66];   // [k][c] padded (even stride for float2 reads)
    __shared__ float  bs[64];

    const int tid = threadIdx.x;
    const int b0 = (tid & 7) * 4;
    const int h0 = (tid >> 3) * 8;
    const int gr = tid;             // c-row this thread generates

    // per-tile sampled bias: e = n*N + c
    {
        int c = c0 + tid;
        float eps = tf_normal(bk0, bk1, (unsigned)(n * N + c));
        bs[tid] = fmaf(eps, expf(vb[c]), mub[c]);
    }

    unsigned long long acc[4][4];
#pragma unroll
    for (int i = 0; i < 4; i++)
#pragma unroll
        for (int j = 0; j < 4; j++) acc[i][j] = 0ull;

    const unsigned erow = (unsigned)(n * N + c0 + gr) * (unsigned)K;
    const float* muRow = mu + (long long)(c0 + gr) * K;
    const float* sRow  = s  + (long long)(c0 + gr) * K;

    for (int k0 = 0; k0 < K; k0 += 32) {
        // ---- x tile: 32b x 32k, duplicated float2 (4 float4 per thread) ----
        {
            int idx = tid;
#pragma unroll
            for (int t = 0; t < 4; t++) {
                int r = idx >> 3, c4 = idx & 7;
                float4 xv = *reinterpret_cast<const float4*>(Xn + r * K + k0 + c4 * 4);
                xs[c4 * 4 + 0][r] = make_float2(xv.x, xv.x);
                xs[c4 * 4 + 1][r] = make_float2(xv.y, xv.y);
                xs[c4 * 4 + 2][r] = make_float2(xv.z, xv.z);
                xs[c4 * 4 + 3][r] = make_float2(xv.w, xv.w);
                idx += 64;
            }
        }
        // ---- generate 64c x 32k weight tile: thread = full c-row, 8 quads ----
#pragma unroll
        for (int q = 0; q < 8; q++) {
            int kk = q * 4;
            float r4[4];
            tf_normal4(wk0, wk1, erow + (unsigned)(k0 + kk), r4);
            float4 m  = *reinterpret_cast<const float4*>(muRow + k0 + kk);
            float4 sv = *reinterpret_cast<const float4*>(sRow  + k0 + kk);
            ws[kk + 0][gr] = fmaf(r4[0], sv.x, m.x);
            ws[kk + 1][gr] = fmaf(r4[1], sv.y, m.y);
            ws[kk + 2][gr] = fmaf(r4[2], sv.z, m.z);
            ws[kk + 3][gr] = fmaf(r4[3], sv.w, m.w);
        }
        __syncthreads();

        // ---- packed-f32x2 FMA: 8 LDS.64 -> 32 FFMA2 per thread ----
#pragma unroll 4
        for (int kk = 0; kk < 32; kk++) {
            unsigned long long xd[4], wd[4];
#pragma unroll
            for (int i = 0; i < 4; i++)
                xd[i] = *reinterpret_cast<const unsigned long long*>(&xs[kk][b0 + i]);
#pragma unroll
            for (int j = 0; j < 4; j++)
                wd[j] = *reinterpret_cast<const unsigned long long*>(&ws[kk][h0 + 2 * j]);
#pragma unroll
            for (int i = 0; i < 4; i++)
#pragma unroll
                for (int j = 0; j < 4; j++)
                    acc[i][j] = ffma2(xd[i], wd[j], acc[i][j]);
        }
        __syncthreads();
    }

#pragma unroll
    for (int j = 0; j < 4; j++) {
        float bj0 = bs[h0 + 2 * j];
        float bj1 = bs[h0 + 2 * j + 1];
#pragma unroll
        for (int i = 0; i < 4; i++) {
            float2 v = unpack2(acc[i][j]);
            v.x += bj0; v.y += bj1;
            if (RELU) { v.x = fmaxf(v.x, 0.0f); v.y = fmaxf(v.y, 0.0f); }
            *reinterpret_cast<float2*>(
                Out + ((long long)n * BATCH + (b0 + i)) * N + c0 + h0 + 2 * j) = v;
        }
    }
}

// -------------------- host-side threefry for subkey derivation --------------------
static inline unsigned h_rotl(unsigned x, int r) { return (x << r) | (x >> (32 - r)); }
static void h_tf2x32(unsigned k0, unsigned k1, unsigned x0, unsigned x1,
                     unsigned& o0, unsigned& o1)
{
    const unsigned ks2 = k0 ^ k1 ^ 0x1BD11BDAu;
    x0 += k0; x1 += k1;
    static const int R[2][4] = {{13, 15, 26, 6}, {17, 29, 16, 24}};
    const unsigned ks[3] = {k0, k1, ks2};
    for (int g = 0; g < 5; g++) {
        for (int r = 0; r < 4; r++) {
            x0 += x1; x1 = h_rotl(x1, R[g & 1][r]); x1 ^= x0;
        }
        x0 += ks[(g + 1) % 3];
        x1 += ks[(g + 2) % 3] + (unsigned)(g + 1);
    }
    o0 = x0; o1 = x1;
}

extern "C" void kernel_launch(void* const* d_in, const int* in_sizes, int n_in,
                              void* d_out, int out_size)
{
    const float* x    = (const float*)d_in[0];
    const float* muW1 = (const float*)d_in[1];
    const float* mub1 = (const float*)d_in[2];
    const float* muW2 = (const float*)d_in[3];
    const float* mub2 = (const float*)d_in[4];
    const float* vW1  = (const float*)d_in[5];
    const float* vb1  = (const float*)d_in[6];
    const float* vW2  = (const float*)d_in[7];
    const float* vb2  = (const float*)d_in[8];
    float* out = (float*)d_out;

    unsigned keys[4][2];
    for (unsigned i = 0; i < 4; i++)
        h_tf2x32(0u, 42u, 0u, i, keys[i][0], keys[i][1]);

    float *sW1, *sW2, *H;
    cudaGetSymbolAddress((void**)&sW1, g_sW1);
    cudaGetSymbolAddress((void**)&sW2, g_sW2);
    cudaGetSymbolAddress((void**)&H,   g_H);

    prep_kernel<<<(DH * DIN + 255) / 256, 256>>>(vW1, vW2);

    // layer 1: h = relu(x @ W1^T + b1) — 1200 blocks of 64 threads (8/SM)
    fused_kernel<DIN, DH, true><<<dim3(NS, DH / 64), 64>>>(
        x, 0LL, muW1, sW1, mub1, vb1, H,
        keys[0][0], keys[0][1], keys[1][0], keys[1][1]);

    // layer 2: y = h @ W2^T + b2 — 600 blocks of 64 threads
    fused_kernel<DH, DOUT, false><<<dim3(NS, DOUT / 64), 64>>>(
        H, (long long)(BATCH * DH), muW2, sW2, mub2, vb2, out,
        keys[2][0], keys[2][1], keys[3][0], keys[3][1]);
}

// round 8
// speedup vs baseline: 1.3808x; 1.0590x over previous
#include <cuda_runtime.h>
#include <cuda_bf16.h>

#define NS    150
#define BATCH 32
#define DIN   1024
#define DH    512
#define DOUT  256

// -------------------- scratch (no cudaMalloc allowed) --------------------
__device__ float g_sW1[DH * DIN];        // exp(v_W1), sample-invariant
__device__ float g_sW2[DOUT * DH];       // exp(v_W2)
__device__ float g_H[NS * BATCH * DH];   // hidden activations

// -------------------- threefry2x32 (JAX-exact, frozen) --------------------
__device__ __forceinline__ void tf2x32(unsigned k0, unsigned k1,
                                       unsigned x0, unsigned x1,
                                       unsigned& o0, unsigned& o1)
{
    const unsigned ks2 = k0 ^ k1 ^ 0x1BD11BDAu;
    x0 += k0; x1 += k1;
#define TF_RND(r) { x0 += x1; x1 = __funnelshift_l(x1, x1, (r)); x1 ^= x0; }
    TF_RND(13) TF_RND(15) TF_RND(26) TF_RND(6)   x0 += k1;  x1 += ks2 + 1u;
    TF_RND(17) TF_RND(29) TF_RND(16) TF_RND(24)  x0 += ks2; x1 += k0  + 2u;
    TF_RND(13) TF_RND(15) TF_RND(26) TF_RND(6)   x0 += k0;  x1 += k1  + 3u;
    TF_RND(17) TF_RND(29) TF_RND(16) TF_RND(24)  x0 += k1;  x1 += ks2 + 4u;
    TF_RND(13) TF_RND(15) TF_RND(26) TF_RND(6)   x0 += ks2; x1 += k0  + 5u;
#undef TF_RND
    o0 = x0; o1 = x1;
}

// bits -> uniform(lo,1) -> sqrt(2)*erfinv (sqrt2 folded into coefficients).
__device__ __forceinline__ float bits_to_normal(unsigned bits)
{
    float f = __uint_as_float((bits >> 9) | 0x3f800000u) - 1.0f;
    float x = fmaf(f, 2.0f, -0.99999994f);

    float w = -__logf(fmaf(-x, x, 1.0f));
    float p;
    if (__builtin_expect(w < 5.0f, 1)) {
        w -= 2.5f;
        p = 3.9742706e-08f;
        p = fmaf(p, w, 4.8546428e-07f);
        p = fmaf(p, w, -4.9828470e-06f);
        p = fmaf(p, w, -6.2105274e-06f);
        p = fmaf(p, w, 3.0912157e-04f);
        p = fmaf(p, w, -1.7730353e-03f);
        p = fmaf(p, w, -5.9081528e-03f);
        p = fmaf(p, w, 3.4876418e-01f);
        p = fmaf(p, w, 2.1233185e+00f);
    } else {
        w = sqrtf(w) - 3.0f;
        p = -2.8314684e-04f;
        p = fmaf(p, w, 1.4276577e-04f);
        p = fmaf(p, w, 1.9082628e-03f);
        p = fmaf(p, w, -5.1950289e-03f);
        p = fmaf(p, w, 8.1169003e-03f);
        p = fmaf(p, w, -1.0779794e-02f);
        p = fmaf(p, w, 1.3348587e-02f);
        p = fmaf(p, w, 1.4165829e+00f);
        p = fmaf(p, w, 4.0064237e+00f);
    }
    return p * x;
}

__device__ __forceinline__ float tf_normal(unsigned k0, unsigned k1, unsigned e)
{
    unsigned o0, o1;
    tf2x32(k0, k1, 0u, e, o0, o1);
    return bits_to_normal(o0 ^ o1);
}

// 4 interleaved threefry chains -> ILP 4 on the ALU dependency chain.
__device__ __forceinline__ void tf_normal4(unsigned k0, unsigned k1, unsigned e,
                                           float r[4])
{
    const unsigned ks2 = k0 ^ k1 ^ 0x1BD11BDAu;
    unsigned a[4], b[4];
#pragma unroll
    for (int i = 0; i < 4; i++) { a[i] = k0; b[i] = (e + (unsigned)i) + k1; }

#define TF_R4(rr) _Pragma("unroll") \
    for (int i = 0; i < 4; i++) { a[i] += b[i]; b[i] = __funnelshift_l(b[i], b[i], (rr)); b[i] ^= a[i]; }
#define TF_INJ4(ka, kb, g) _Pragma("unroll") \
    for (int i = 0; i < 4; i++) { a[i] += (ka); b[i] += (kb) + (g); }

    TF_R4(13) TF_R4(15) TF_R4(26) TF_R4(6)   TF_INJ4(k1,  ks2, 1u)
    TF_R4(17) TF_R4(29) TF_R4(16) TF_R4(24)  TF_INJ4(ks2, k0,  2u)
    TF_R4(13) TF_R4(15) TF_R4(26) TF_R4(6)   TF_INJ4(k0,  k1,  3u)
    TF_R4(17) TF_R4(29) TF_R4(16) TF_R4(24)  TF_INJ4(k1,  ks2, 4u)
    TF_R4(13) TF_R4(15) TF_R4(26) TF_R4(6)   TF_INJ4(ks2, k0,  5u)
#undef TF_R4
#undef TF_INJ4

#pragma unroll
    for (int i = 0; i < 4; i++) r[i] = bits_to_normal(a[i] ^ b[i]);
}

// -------------------- packed f32x2 helpers --------------------
__device__ __forceinline__ unsigned long long ffma2(unsigned long long a,
                                                    unsigned long long b,
                                                    unsigned long long c)
{
    unsigned long long d;
    asm("fma.rn.f32x2 %0, %1, %2, %3;" : "=l"(d) : "l"(a), "l"(b), "l"(c));
    return d;
}
__device__ __forceinline__ float2 unpack2(unsigned long long d)
{
    unsigned lo, hi;
    asm("mov.b64 {%0, %1}, %2;" : "=r"(lo), "=r"(hi) : "l"(d));
    return make_float2(__uint_as_float(lo), __uint_as_float(hi));
}

// -------------------- exp(v_W) precompute (bit-identical expf) --------------------
__global__ __launch_bounds__(256) void prep_kernel(const float* __restrict__ vW1,
                                                   const float* __restrict__ vW2)
{
    int i = blockIdx.x * 256 + threadIdx.x;
    if (i < DH * DIN)  g_sW1[i] = expf(vW1[i]);
    if (i < DOUT * DH) g_sW2[i] = expf(vW2[i]);
}

// -------------------- fused sample-and-GEMM, software-pipelined --------------------
// Double-buffered ws: generation of tile k0+32 (ALU pipe) interleaves with
// FMA on tile k0 (FMA pipe) in the same instruction window -> both pipes co-issue.
// 128 threads; thread tile = 4b x (CTILE/16)c; operands via LDS.128.
template<int K, int N, int CTILE, bool RELU>
__global__ __launch_bounds__(128, 4) void fused_kernel(
    const float* __restrict__ X, long long xStride,
    const float* __restrict__ mu, const float* __restrict__ s,
    const float* __restrict__ mub, const float* __restrict__ vb,
    float* __restrict__ Out,
    unsigned wk0, unsigned wk1, unsigned bk0, unsigned bk1)
{
    constexpr int HALVES = 128 / CTILE;   // 1 (CTILE=128) or 2 (CTILE=64)
    constexpr int KSEG   = 32 / HALVES;   // 32 or 16 k-values generated per thread
    constexpr int NQ     = KSEG / 4;      // quads per thread per k0: 8 or 4
    constexpr int QSTEP  = 8 / NQ;        // gen every QSTEP-th q: 1 or 2
    constexpr int CP     = CTILE / 32;    // f32x2 accumulator pairs: 4 or 2

    __shared__ float2 xs[32][34];                 // [k][b] duplicated, 16B-aligned rows
    __shared__ float  ws[2][32][CTILE + 4];       // double-buffered, 16B-aligned rows
    __shared__ float  bs[CTILE];

    const int n  = blockIdx.x;
    const int c0 = blockIdx.y * CTILE;
    const float* Xn = X + (long long)n * xStride;

    const int tid = threadIdx.x;
    const int b0  = (tid & 7) * 4;
    const int h0  = (tid >> 3) * (CP * 2);
    const int gr  = tid % CTILE;
    const int gk0 = (tid / CTILE) * KSEG;

    // per-tile sampled bias: e = n*N + c
    if (tid < CTILE) {
        int c = c0 + tid;
        float eps = tf_normal(bk0, bk1, (unsigned)(n * N + c));
        bs[tid] = fmaf(eps, expf(vb[c]), mub[c]);
    }

    unsigned long long acc[4][CP];
#pragma unroll
    for (int i = 0; i < 4; i++)
#pragma unroll
        for (int j = 0; j < CP; j++) acc[i][j] = 0ull;

    const unsigned erow = (unsigned)(n * N + c0 + gr) * (unsigned)K + (unsigned)gk0;
    const float* muRow = mu + (long long)(c0 + gr) * K + gk0;
    const float* sRow  = s  + (long long)(c0 + gr) * K + gk0;

    const int xr = tid >> 3, xc = (tid & 7) * 4;  // x-load mapping (2 float4/thread)

    // ---- prologue: prefetch x(0), generate ws[0] for k0=0 ----
    float4 xp0 = *reinterpret_cast<const float4*>(Xn + xr * K + xc);
    float4 xp1 = *reinterpret_cast<const float4*>(Xn + (xr + 16) * K + xc);
#pragma unroll 1
    for (int qq = 0; qq < NQ; qq++) {
        float r4[4];
        tf_normal4(wk0, wk1, erow + (unsigned)(qq * 4), r4);
        float4 m  = *reinterpret_cast<const float4*>(muRow + qq * 4);
        float4 sv = *reinterpret_cast<const float4*>(sRow  + qq * 4);
        int kk = gk0 + qq * 4;
        ws[0][kk + 0][gr] = fmaf(r4[0], sv.x, m.x);
        ws[0][kk + 1][gr] = fmaf(r4[1], sv.y, m.y);
        ws[0][kk + 2][gr] = fmaf(r4[2], sv.z, m.z);
        ws[0][kk + 3][gr] = fmaf(r4[3], sv.w, m.w);
    }
    xs[xc + 0][xr] = make_float2(xp0.x, xp0.x);
    xs[xc + 1][xr] = make_float2(xp0.y, xp0.y);
    xs[xc + 2][xr] = make_float2(xp0.z, xp0.z);
    xs[xc + 3][xr] = make_float2(xp0.w, xp0.w);
    xs[xc + 0][xr + 16] = make_float2(xp1.x, xp1.x);
    xs[xc + 1][xr + 16] = make_float2(xp1.y, xp1.y);
    xs[xc + 2][xr + 16] = make_float2(xp1.z, xp1.z);
    xs[xc + 3][xr + 16] = make_float2(xp1.w, xp1.w);
    __syncthreads();

    // ---- main loop: interleave gen(k0+32) with FMA(k0) ----
    for (int k0 = 0; k0 < K; k0 += 32) {
        const int cur = (k0 >> 5) & 1;
        const int nxt = cur ^ 1;
        const bool more = (k0 + 32) < K;

        if (more) {   // prefetch next x tile; latency hides under gen+FMA below
            xp0 = *reinterpret_cast<const float4*>(Xn + xr * K + k0 + 32 + xc);
            xp1 = *reinterpret_cast<const float4*>(Xn + (xr + 16) * K + k0 + 32 + xc);
        }

#pragma unroll 1
        for (int q = 0; q < 8; q++) {
            if (more && (q % QSTEP) == 0) {          // ALU-pipe work
                const int qq = q / QSTEP;
                float r4[4];
                tf_normal4(wk0, wk1, erow + (unsigned)(k0 + 32 + qq * 4), r4);
                float4 m  = *reinterpret_cast<const float4*>(muRow + k0 + 32 + qq * 4);
                float4 sv = *reinterpret_cast<const float4*>(sRow  + k0 + 32 + qq * 4);
                int kk = gk0 + qq * 4;
                ws[nxt][kk + 0][gr] = fmaf(r4[0], sv.x, m.x);
                ws[nxt][kk + 1][gr] = fmaf(r4[1], sv.y, m.y);
                ws[nxt][kk + 2][gr] = fmaf(r4[2], sv.z, m.z);
                ws[nxt][kk + 3][gr] = fmaf(r4[3], sv.w, m.w);
            }
#pragma unroll                                        // FMA-pipe work
            for (int kk = q * 4; kk < q * 4 + 4; kk++) {
                unsigned long long xd[4], wd[CP];
                {
                    ulonglong2 t0 = *reinterpret_cast<const ulonglong2*>(&xs[kk][b0]);
                    ulonglong2 t1 = *reinterpret_cast<const ulonglong2*>(&xs[kk][b0 + 2]);
                    xd[0] = t0.x; xd[1] = t0.y; xd[2] = t1.x; xd[3] = t1.y;
                }
                if (CP == 4) {
                    ulonglong2 t0 = *reinterpret_cast<const ulonglong2*>(&ws[cur][kk][h0]);
                    ulonglong2 t1 = *reinterpret_cast<const ulonglong2*>(&ws[cur][kk][h0 + 4]);
                    wd[0] = t0.x; wd[1] = t0.y; wd[2] = t1.x; wd[3] = t1.y;
                } else {
                    ulonglong2 t0 = *reinterpret_cast<const ulonglong2*>(&ws[cur][kk][h0]);
                    wd[0] = t0.x; wd[1] = t0.y;
                }
#pragma unroll
                for (int i = 0; i < 4; i++)
#pragma unroll
                    for (int j = 0; j < CP; j++)
                        acc[i][j] = ffma2(xd[i], wd[j], acc[i][j]);
            }
        }
        __syncthreads();
        if (more) {   // short region: store prefetched x tile (duplicated)
            xs[xc + 0][xr] = make_float2(xp0.x, xp0.x);
            xs[xc + 1][xr] = make_float2(xp0.y, xp0.y);
            xs[xc + 2][xr] = make_float2(xp0.z, xp0.z);
            xs[xc + 3][xr] = make_float2(xp0.w, xp0.w);
            xs[xc + 0][xr + 16] = make_float2(xp1.x, xp1.x);
            xs[xc + 1][xr + 16] = make_float2(xp1.y, xp1.y);
            xs[xc + 2][xr + 16] = make_float2(xp1.z, xp1.z);
            xs[xc + 3][xr + 16] = make_float2(xp1.w, xp1.w);
        }
        __syncthreads();
    }

    // ---- epilogue: bias + (relu) + store ----
#pragma unroll
    for (int j = 0; j < CP; j++) {
        float bj0 = bs[h0 + 2 * j];
        float bj1 = bs[h0 + 2 * j + 1];
#pragma unroll
        for (int i = 0; i < 4; i++) {
            float2 v = unpack2(acc[i][j]);
            v.x += bj0; v.y += bj1;
            if (RELU) { v.x = fmaxf(v.x, 0.0f); v.y = fmaxf(v.y, 0.0f); }
            *reinterpret_cast<float2*>(
                Out + ((long long)n * BATCH + (b0 + i)) * N + c0 + h0 + 2 * j) = v;
        }
    }
}

// -------------------- host-side threefry for subkey derivation --------------------
static inline unsigned h_rotl(unsigned x, int r) { return (x << r) | (x >> (32 - r)); }
static void h_tf2x32(unsigned k0, unsigned k1, unsigned x0, unsigned x1,
                     unsigned& o0, unsigned& o1)
{
    const unsigned ks2 = k0 ^ k1 ^ 0x1BD11BDAu;
    x0 += k0; x1 += k1;
    static const int R[2][4] = {{13, 15, 26, 6}, {17, 29, 16, 24}};
    const unsigned ks[3] = {k0, k1, ks2};
    for (int g = 0; g < 5; g++) {
        for (int r = 0; r < 4; r++) {
            x0 += x1; x1 = h_rotl(x1, R[g & 1][r]); x1 ^= x0;
        }
        x0 += ks[(g + 1) % 3];
        x1 += ks[(g + 2) % 3] + (unsigned)(g + 1);
    }
    o0 = x0; o1 = x1;
}

extern "C" void kernel_launch(void* const* d_in, const int* in_sizes, int n_in,
                              void* d_out, int out_size)
{
    const float* x    = (const float*)d_in[0];
    const float* muW1 = (const float*)d_in[1];
    const float* mub1 = (const float*)d_in[2];
    const float* muW2 = (const float*)d_in[3];
    const float* mub2 = (const float*)d_in[4];
    const float* vW1  = (const float*)d_in[5];
    const float* vb1  = (const float*)d_in[6];
    const float* vW2  = (const float*)d_in[7];
    const float* vb2  = (const float*)d_in[8];
    float* out = (float*)d_out;

    unsigned keys[4][2];
    for (unsigned i = 0; i < 4; i++)
        h_tf2x32(0u, 42u, 0u, i, keys[i][0], keys[i][1]);

    float *sW1, *sW2, *H;
    cudaGetSymbolAddress((void**)&sW1, g_sW1);
    cudaGetSymbolAddress((void**)&sW2, g_sW2);
    cudaGetSymbolAddress((void**)&H,   g_H);

    prep_kernel<<<(DH * DIN + 255) / 256, 256>>>(vW1, vW2);

    // layer 1: h = relu(x @ W1^T + b1), CTILE=128 -> grid 150x4
    fused_kernel<DIN, DH, 128, true><<<dim3(NS, DH / 128), 128>>>(
        x, 0LL, muW1, sW1, mub1, vb1, H,
        keys[0][0], keys[0][1], keys[1][0], keys[1][1]);

    // layer 2: y = h @ W2^T + b2, CTILE=64 -> grid 150x4
    fused_kernel<DH, DOUT, 64, false><<<dim3(NS, DOUT / 64), 128>>>(
        H, (long long)(BATCH * DH), muW2, sW2, mub2, vb2, out,
        keys[2][0], keys[2][1], keys[3][0], keys[3][1]);
}

// round 10
// speedup vs baseline: 1.5683x; 1.1358x over previous
#include <cuda_runtime.h>
#include <cuda_bf16.h>
#include <mma.h>
#include <cstdint>

using namespace nvcuda;

#define NS    150
#define BATCH 32
#define DIN   1024
#define DH    512
#define DOUT  256

// -------------------- scratch (no cudaMalloc allowed) --------------------
__device__ float g_sW1[DH * DIN];                 // exp(v_W1)
__device__ float g_sW2[DOUT * DH];                // exp(v_W2)
__device__ __nv_bfloat16 g_xhi[BATCH * DIN];      // x split hi
__device__ __nv_bfloat16 g_xlo[BATCH * DIN];      // x split lo
__device__ __nv_bfloat16 g_Hhi[NS * BATCH * DH];  // h split hi
__device__ __nv_bfloat16 g_Hlo[NS * BATCH * DH];  // h split lo

// -------------------- threefry2x32 (JAX-exact, frozen) --------------------
__device__ __forceinline__ void tf2x32(unsigned k0, unsigned k1,
                                       unsigned x0, unsigned x1,
                                       unsigned& o0, unsigned& o1)
{
    const unsigned ks2 = k0 ^ k1 ^ 0x1BD11BDAu;
    x0 += k0; x1 += k1;
#define TF_RND(r) { x0 += x1; x1 = __funnelshift_l(x1, x1, (r)); x1 ^= x0; }
    TF_RND(13) TF_RND(15) TF_RND(26) TF_RND(6)   x0 += k1;  x1 += ks2 + 1u;
    TF_RND(17) TF_RND(29) TF_RND(16) TF_RND(24)  x0 += ks2; x1 += k0  + 2u;
    TF_RND(13) TF_RND(15) TF_RND(26) TF_RND(6)   x0 += k0;  x1 += k1  + 3u;
    TF_RND(17) TF_RND(29) TF_RND(16) TF_RND(24)  x0 += k1;  x1 += ks2 + 4u;
    TF_RND(13) TF_RND(15) TF_RND(26) TF_RND(6)   x0 += ks2; x1 += k0  + 5u;
#undef TF_RND
    o0 = x0; o1 = x1;
}

__device__ __forceinline__ float bits_to_normal(unsigned bits)
{
    float f = __uint_as_float((bits >> 9) | 0x3f800000u) - 1.0f;
    float x = fmaf(f, 2.0f, -0.99999994f);
    float w = -__logf(fmaf(-x, x, 1.0f));
    float p;
    if (__builtin_expect(w < 5.0f, 1)) {
        w -= 2.5f;
        p = 3.9742706e-08f;
        p = fmaf(p, w, 4.8546428e-07f);
        p = fmaf(p, w, -4.9828470e-06f);
        p = fmaf(p, w, -6.2105274e-06f);
        p = fmaf(p, w, 3.0912157e-04f);
        p = fmaf(p, w, -1.7730353e-03f);
        p = fmaf(p, w, -5.9081528e-03f);
        p = fmaf(p, w, 3.4876418e-01f);
        p = fmaf(p, w, 2.1233185e+00f);
    } else {
        w = sqrtf(w) - 3.0f;
        p = -2.8314684e-04f;
        p = fmaf(p, w, 1.4276577e-04f);
        p = fmaf(p, w, 1.9082628e-03f);
        p = fmaf(p, w, -5.1950289e-03f);
        p = fmaf(p, w, 8.1169003e-03f);
        p = fmaf(p, w, -1.0779794e-02f);
        p = fmaf(p, w, 1.3348587e-02f);
        p = fmaf(p, w, 1.4165829e+00f);
        p = fmaf(p, w, 4.0064237e+00f);
    }
    return p * x;
}

__device__ __forceinline__ float tf_normal(unsigned k0, unsigned k1, unsigned e)
{
    unsigned o0, o1;
    tf2x32(k0, k1, 0u, e, o0, o1);
    return bits_to_normal(o0 ^ o1);
}

// 4 interleaved threefry chains -> ILP 4 on the ALU dependency chain.
__device__ __forceinline__ void tf_normal4(unsigned k0, unsigned k1, unsigned e,
                                           float r[4])
{
    const unsigned ks2 = k0 ^ k1 ^ 0x1BD11BDAu;
    unsigned a[4], b[4];
#pragma unroll
    for (int i = 0; i < 4; i++) { a[i] = k0; b[i] = (e + (unsigned)i) + k1; }
#define TF_R4(rr) _Pragma("unroll") \
    for (int i = 0; i < 4; i++) { a[i] += b[i]; b[i] = __funnelshift_l(b[i], b[i], (rr)); b[i] ^= a[i]; }
#define TF_INJ4(ka, kb, g) _Pragma("unroll") \
    for (int i = 0; i < 4; i++) { a[i] += (ka); b[i] += (kb) + (g); }
    TF_R4(13) TF_R4(15) TF_R4(26) TF_R4(6)   TF_INJ4(k1,  ks2, 1u)
    TF_R4(17) TF_R4(29) TF_R4(16) TF_R4(24)  TF_INJ4(ks2, k0,  2u)
    TF_R4(13) TF_R4(15) TF_R4(26) TF_R4(6)   TF_INJ4(k0,  k1,  3u)
    TF_R4(17) TF_R4(29) TF_R4(16) TF_R4(24)  TF_INJ4(k1,  ks2, 4u)
    TF_R4(13) TF_R4(15) TF_R4(26) TF_R4(6)   TF_INJ4(ks2, k0,  5u)
#undef TF_R4
#undef TF_INJ4
#pragma unroll
    for (int i = 0; i < 4; i++) r[i] = bits_to_normal(a[i] ^ b[i]);
}

__device__ __forceinline__ unsigned pack_bf16x2(float hi, float lo)
{
    unsigned r;
    asm("cvt.rn.bf16x2.f32 %0, %1, %2;" : "=r"(r) : "f"(hi), "f"(lo));
    return r;
}

// -------------------- prep: exp(v_W), x bf16 split --------------------
__global__ __launch_bounds__(256) void prep_kernel(const float* __restrict__ x,
                                                   const float* __restrict__ vW1,
                                                   const float* __restrict__ vW2)
{
    int i = blockIdx.x * 256 + threadIdx.x;
    if (i < DH * DIN)  g_sW1[i] = expf(vW1[i]);
    if (i < DOUT * DH) g_sW2[i] = expf(vW2[i]);
    if (i < BATCH * DIN) {
        float xv = x[i];
        __nv_bfloat16 hi = __float2bfloat16_rn(xv);
        __nv_bfloat16 lo = __float2bfloat16_rn(xv - __bfloat162float(hi));
        g_xhi[i] = hi; g_xlo[i] = lo;
    }
}

// -------------------- fused: sample W -> split bf16 -> wmma (HMMA) --------------------
// D[c, b] = sum_k W[c,k] * X[b,k]; split scheme D ≈ Whi·Xhi + Whi·Xlo + Wlo·Xhi.
// 128 threads, CTILE=64 c-rows per block; warp w owns m-block w (16 c), 2 n-blocks.
template<int K, int NOUT, bool LAST>
__global__ __launch_bounds__(128, 4) void fused_wmma(
    const float* __restrict__ mu, const float* __restrict__ s,
    const float* __restrict__ mub, const float* __restrict__ vb,
    const __nv_bfloat16* __restrict__ Bhi, const __nv_bfloat16* __restrict__ Blo,
    float* __restrict__ Out,
    unsigned wk0, unsigned wk1, unsigned bk0, unsigned bk1, long long bStride)
{
    constexpr int CTILE = 64;
    constexpr int KCH = 32;       // k chunk
    constexpr int WST = 40;       // W smem stride in bf16 (80B: conflict-free ldmatrix)
    constexpr int DST = 36;       // D smem stride in f32

    __shared__ __nv_bfloat16 Whi[CTILE * WST];
    __shared__ __nv_bfloat16 Wlo[CTILE * WST];
    __shared__ float Dsm[CTILE * DST];

    const int tid  = threadIdx.x;
    const int warp = tid >> 5;
    const int n = blockIdx.x, c0 = blockIdx.y * CTILE;

    const int gr = tid & 63;            // c-row this thread generates
    const int gk = (tid >> 6) * 16;     // k half within chunk (0 or 16)

    // per-row sampled bias (kept in register; e = n*NOUT + c)
    float bias;
    {
        int c = c0 + gr;
        float eps = tf_normal(bk0, bk1, (unsigned)(n * NOUT + c));
        bias = fmaf(eps, expf(vb[c]), mub[c]);
    }

    wmma::fragment<wmma::accumulator, 16, 16, 16, float> acc[2];
    wmma::fill_fragment(acc[0], 0.0f);
    wmma::fill_fragment(acc[1], 0.0f);

    const unsigned erow = (unsigned)(n * NOUT + c0 + gr) * (unsigned)K + (unsigned)gk;
    const float* muRow = mu + (size_t)(c0 + gr) * K + gk;
    const float* sRow  = s  + (size_t)(c0 + gr) * K + gk;
    const __nv_bfloat16* bh = Bhi + (size_t)n * bStride;
    const __nv_bfloat16* bl = Blo + (size_t)n * bStride;

    for (int k0 = 0; k0 < K; k0 += KCH) {
        // ---- generate + split W chunk: 64c x 32k (thread: 16 k in 4 quads) ----
#pragma unroll
        for (int q = 0; q < 4; q++) {
            float r4[4];
            tf_normal4(wk0, wk1, erow + (unsigned)(k0 + q * 4), r4);
            float4 m  = *reinterpret_cast<const float4*>(muRow + k0 + q * 4);
            float4 sv = *reinterpret_cast<const float4*>(sRow  + k0 + q * 4);
            float w0 = fmaf(r4[0], sv.x, m.x);
            float w1 = fmaf(r4[1], sv.y, m.y);
            float w2 = fmaf(r4[2], sv.z, m.z);
            float w3 = fmaf(r4[3], sv.w, m.w);
            unsigned hp0 = pack_bf16x2(w1, w0);
            unsigned hp1 = pack_bf16x2(w3, w2);
            float h0 = __uint_as_float(hp0 << 16);
            float h1 = __uint_as_float(hp0 & 0xFFFF0000u);
            float h2 = __uint_as_float(hp1 << 16);
            float h3 = __uint_as_float(hp1 & 0xFFFF0000u);
            unsigned lp0 = pack_bf16x2(w1 - h1, w0 - h0);
            unsigned lp1 = pack_bf16x2(w3 - h3, w2 - h2);
            int off = gr * WST + gk + q * 4;
            *reinterpret_cast<uint2*>(&Whi[off]) = make_uint2(hp0, hp1);
            *reinterpret_cast<uint2*>(&Wlo[off]) = make_uint2(lp0, lp1);
        }
        __syncthreads();

        // ---- tensor-pipe GEMM on the chunk: 2 k16 steps ----
#pragma unroll
        for (int kk = 0; kk < KCH; kk += 16) {
            wmma::fragment<wmma::matrix_a, 16, 16, 16, __nv_bfloat16, wmma::row_major> ahi, alo;
            wmma::load_matrix_sync(ahi, &Whi[warp * 16 * WST + kk], WST);
            wmma::load_matrix_sync(alo, &Wlo[warp * 16 * WST + kk], WST);
#pragma unroll
            for (int nb = 0; nb < 2; nb++) {
                wmma::fragment<wmma::matrix_b, 16, 16, 16, __nv_bfloat16, wmma::col_major> bhf, blf;
                wmma::load_matrix_sync(bhf, bh + (size_t)(nb * 16) * K + (k0 + kk), K);
                wmma::load_matrix_sync(blf, bl + (size_t)(nb * 16) * K + (k0 + kk), K);
                wmma::mma_sync(acc[nb], ahi, bhf, acc[nb]);
                wmma::mma_sync(acc[nb], ahi, blf, acc[nb]);
                wmma::mma_sync(acc[nb], alo, bhf, acc[nb]);
            }
        }
        __syncthreads();
    }

    // ---- D -> smem -> epilogue ----
    wmma::store_matrix_sync(&Dsm[warp * 16 * DST + 0],  acc[0], DST, wmma::mem_row_major);
    wmma::store_matrix_sync(&Dsm[warp * 16 * DST + 16], acc[1], DST, wmma::mem_row_major);
    __syncthreads();

    {
        const int c  = gr;
        const int b0 = (tid >> 6) * 16;
#pragma unroll
        for (int b = b0; b < b0 + 16; b++) {
            float v = Dsm[c * DST + b] + bias;
            if (!LAST) {
                v = fmaxf(v, 0.0f);
                __nv_bfloat16 hi = __float2bfloat16_rn(v);
                __nv_bfloat16 lo = __float2bfloat16_rn(v - __bfloat162float(hi));
                size_t o = ((size_t)n * BATCH + b) * NOUT + (c0 + c);
                g_Hhi[o] = hi; g_Hlo[o] = lo;
            } else {
                Out[((size_t)n * BATCH + b) * NOUT + (c0 + c)] = v;
            }
        }
    }
}

// -------------------- host-side threefry for subkey derivation --------------------
static inline unsigned h_rotl(unsigned x, int r) { return (x << r) | (x >> (32 - r)); }
static void h_tf2x32(unsigned k0, unsigned k1, unsigned x0, unsigned x1,
                     unsigned& o0, unsigned& o1)
{
    const unsigned ks2 = k0 ^ k1 ^ 0x1BD11BDAu;
    x0 += k0; x1 += k1;
    static const int R[2][4] = {{13, 15, 26, 6}, {17, 29, 16, 24}};
    const unsigned ks[3] = {k0, k1, ks2};
    for (int g = 0; g < 5; g++) {
        for (int r = 0; r < 4; r++) {
            x0 += x1; x1 = h_rotl(x1, R[g & 1][r]); x1 ^= x0;
        }
        x0 += ks[(g + 1) % 3];
        x1 += ks[(g + 2) % 3] + (unsigned)(g + 1);
    }
    o0 = x0; o1 = x1;
}

extern "C" void kernel_launch(void* const* d_in, const int* in_sizes, int n_in,
                              void* d_out, int out_size)
{
    const float* x    = (const float*)d_in[0];
    const float* muW1 = (const float*)d_in[1];
    const float* mub1 = (const float*)d_in[2];
    const float* muW2 = (const float*)d_in[3];
    const float* mub2 = (const float*)d_in[4];
    const float* vW1  = (const float*)d_in[5];
    const float* vb1  = (const float*)d_in[6];
    const float* vW2  = (const float*)d_in[7];
    const float* vb2  = (const float*)d_in[8];
    float* out = (float*)d_out;

    unsigned keys[4][2];
    for (unsigned i = 0; i < 4; i++)
        h_tf2x32(0u, 42u, 0u, i, keys[i][0], keys[i][1]);

    float *sW1, *sW2;
    __nv_bfloat16 *xhi, *xlo, *Hhi, *Hlo;
    cudaGetSymbolAddress((void**)&sW1, g_sW1);
    cudaGetSymbolAddress((void**)&sW2, g_sW2);
    cudaGetSymbolAddress((void**)&xhi, g_xhi);
    cudaGetSymbolAddress((void**)&xlo, g_xlo);
    cudaGetSymbolAddress((void**)&Hhi, g_Hhi);
    cudaGetSymbolAddress((void**)&Hlo, g_Hlo);

    prep_kernel<<<(DH * DIN + 255) / 256, 256>>>(x, vW1, vW2);

    // layer 1: h = relu(x @ W1^T + b1); 1200 blocks
    fused_wmma<DIN, DH, false><<<dim3(NS, DH / 64), 128>>>(
        muW1, sW1, mub1, vb1, xhi, xlo, nullptr,
        keys[0][0], keys[0][1], keys[1][0], keys[1][1], 0LL);

    // layer 2: y = h @ W2^T + b2; 600 blocks
    fused_wmma<DH, DOUT, true><<<dim3(NS, DOUT / 64), 128>>>(
        muW2, sW2, mub2, vb2, Hhi, Hlo, out,
        keys[2][0], keys[2][1], keys[3][0], keys[3][1],
        (long long)(BATCH * DH));
}

// round 11
// speedup vs baseline: 1.7897x; 1.1412x over previous
#include <cuda_runtime.h>
#include <cuda_bf16.h>
#include <mma.h>
#include <cstdint>

using namespace nvcuda;

#define NS    150
#define BATCH 32
#define DIN   1024
#define DH    512
#define DOUT  256

// -------------------- scratch (no cudaMalloc allowed) --------------------
__device__ float g_sW1[DH * DIN];                 // exp(v_W1)
__device__ float g_sW2[DOUT * DH];                // exp(v_W2)
__device__ __nv_bfloat16 g_xhi[BATCH * DIN];      // x split hi
__device__ __nv_bfloat16 g_xlo[BATCH * DIN];      // x split lo
__device__ __nv_bfloat16 g_Hhi[NS * BATCH * DH];  // h split hi
__device__ __nv_bfloat16 g_Hlo[NS * BATCH * DH];  // h split lo

// -------------------- threefry2x32 (JAX-exact, frozen) --------------------
__device__ __forceinline__ void tf2x32(unsigned k0, unsigned k1,
                                       unsigned x0, unsigned x1,
                                       unsigned& o0, unsigned& o1)
{
    const unsigned ks2 = k0 ^ k1 ^ 0x1BD11BDAu;
    x0 += k0; x1 += k1;
#define TF_RND(r) { x0 += x1; x1 = __funnelshift_l(x1, x1, (r)); x1 ^= x0; }
    TF_RND(13) TF_RND(15) TF_RND(26) TF_RND(6)   x0 += k1;  x1 += ks2 + 1u;
    TF_RND(17) TF_RND(29) TF_RND(16) TF_RND(24)  x0 += ks2; x1 += k0  + 2u;
    TF_RND(13) TF_RND(15) TF_RND(26) TF_RND(6)   x0 += k0;  x1 += k1  + 3u;
    TF_RND(17) TF_RND(29) TF_RND(16) TF_RND(24)  x0 += k1;  x1 += ks2 + 4u;
    TF_RND(13) TF_RND(15) TF_RND(26) TF_RND(6)   x0 += ks2; x1 += k0  + 5u;
#undef TF_RND
    o0 = x0; o1 = x1;
}

__device__ __forceinline__ float bits_to_normal(unsigned bits)
{
    float f = __uint_as_float((bits >> 9) | 0x3f800000u) - 1.0f;
    float x = fmaf(f, 2.0f, -0.99999994f);
    float w = -__logf(fmaf(-x, x, 1.0f));
    float p;
    if (__builtin_expect(w < 5.0f, 1)) {
        w -= 2.5f;
        p = 3.9742706e-08f;
        p = fmaf(p, w, 4.8546428e-07f);
        p = fmaf(p, w, -4.9828470e-06f);
        p = fmaf(p, w, -6.2105274e-06f);
        p = fmaf(p, w, 3.0912157e-04f);
        p = fmaf(p, w, -1.7730353e-03f);
        p = fmaf(p, w, -5.9081528e-03f);
        p = fmaf(p, w, 3.4876418e-01f);
        p = fmaf(p, w, 2.1233185e+00f);
    } else {
        w = sqrtf(w) - 3.0f;
        p = -2.8314684e-04f;
        p = fmaf(p, w, 1.4276577e-04f);
        p = fmaf(p, w, 1.9082628e-03f);
        p = fmaf(p, w, -5.1950289e-03f);
        p = fmaf(p, w, 8.1169003e-03f);
        p = fmaf(p, w, -1.0779794e-02f);
        p = fmaf(p, w, 1.3348587e-02f);
        p = fmaf(p, w, 1.4165829e+00f);
        p = fmaf(p, w, 4.0064237e+00f);
    }
    return p * x;
}

__device__ __forceinline__ float tf_normal(unsigned k0, unsigned k1, unsigned e)
{
    unsigned o0, o1;
    tf2x32(k0, k1, 0u, e, o0, o1);
    return bits_to_normal(o0 ^ o1);
}

// 4 interleaved threefry chains -> ILP 4 on the ALU dependency chain.
__device__ __forceinline__ void tf_normal4(unsigned k0, unsigned k1, unsigned e,
                                           float r[4])
{
    const unsigned ks2 = k0 ^ k1 ^ 0x1BD11BDAu;
    unsigned a[4], b[4];
#pragma unroll
    for (int i = 0; i < 4; i++) { a[i] = k0; b[i] = (e + (unsigned)i) + k1; }
#define TF_R4(rr) _Pragma("unroll") \
    for (int i = 0; i < 4; i++) { a[i] += b[i]; b[i] = __funnelshift_l(b[i], b[i], (rr)); b[i] ^= a[i]; }
#define TF_INJ4(ka, kb, g) _Pragma("unroll") \
    for (int i = 0; i < 4; i++) { a[i] += (ka); b[i] += (kb) + (g); }
    TF_R4(13) TF_R4(15) TF_R4(26) TF_R4(6)   TF_INJ4(k1,  ks2, 1u)
    TF_R4(17) TF_R4(29) TF_R4(16) TF_R4(24)  TF_INJ4(ks2, k0,  2u)
    TF_R4(13) TF_R4(15) TF_R4(26) TF_R4(6)   TF_INJ4(k0,  k1,  3u)
    TF_R4(17) TF_R4(29) TF_R4(16) TF_R4(24)  TF_INJ4(k1,  ks2, 4u)
    TF_R4(13) TF_R4(15) TF_R4(26) TF_R4(6)   TF_INJ4(ks2, k0,  5u)
#undef TF_R4
#undef TF_INJ4
#pragma unroll
    for (int i = 0; i < 4; i++) r[i] = bits_to_normal(a[i] ^ b[i]);
}

__device__ __forceinline__ unsigned pack_bf16x2(float hi, float lo)
{
    unsigned r;
    asm("cvt.rn.bf16x2.f32 %0, %1, %2;" : "=r"(r) : "f"(hi), "f"(lo));
    return r;
}

// -------------------- prep: exp(v_W), x bf16 split --------------------
__global__ __launch_bounds__(256) void prep_kernel(const float* __restrict__ x,
                                                   const float* __restrict__ vW1,
                                                   const float* __restrict__ vW2)
{
    int i = blockIdx.x * 256 + threadIdx.x;
    if (i < DH * DIN)  g_sW1[i] = expf(vW1[i]);
    if (i < DOUT * DH) g_sW2[i] = expf(vW2[i]);
    if (i < BATCH * DIN) {
        float xv = x[i];
        __nv_bfloat16 hi = __float2bfloat16_rn(xv);
        __nv_bfloat16 lo = __float2bfloat16_rn(xv - __bfloat162float(hi));
        g_xhi[i] = hi; g_xlo[i] = lo;
    }
}

// -------------------- fused: sample W -> split bf16 -> wmma (HMMA) --------------------
// D[c, b] = sum_k W[c,k] * X[b,k]; split: D ≈ Whi·Xhi + Whi·Xlo + Wlo·Xhi.
// CTILE=64 c-rows/block, 128 threads. Gen mapping coalesced: lane-octet = one
// 128B mu/s line. W smem double-buffered: one barrier per chunk, gen(i+1)
// co-issues with HMMA(i).
template<int K, int NOUT, bool LAST>
__global__ __launch_bounds__(128, 4) void fused_wmma(
    const float* __restrict__ mu, const float* __restrict__ s,
    const float* __restrict__ mub, const float* __restrict__ vb,
    const __nv_bfloat16* __restrict__ Bhi, const __nv_bfloat16* __restrict__ Blo,
    float* __restrict__ Out,
    unsigned wk0, unsigned wk1, unsigned bk0, unsigned bk1, long long bStride)
{
    constexpr int CTILE = 64;
    constexpr int KCH = 32;       // k chunk
    constexpr int WST = 40;       // W smem stride in bf16 (80B)
    constexpr int DST = 36;       // D smem stride in f32

    __shared__ __nv_bfloat16 Whi[2][CTILE * WST];
    __shared__ __nv_bfloat16 Wlo[2][CTILE * WST];
    __shared__ float Dsm[CTILE * DST];

    const int tid  = threadIdx.x;
    const int warp = tid >> 5;
    const int n = blockIdx.x, c0 = blockIdx.y * CTILE;

    // gen mapping: k-quad = tid&7 (lanes 0-7 -> one 128B line), row base = tid>>3
    const int qk    = (tid & 7) * 4;    // k offset within chunk
    const int rbase = tid >> 3;         // row 0..15; +q*16 covers 64 rows

    // epilogue mapping (as R10)
    const int ec = tid & 63;
    const int eb = (tid >> 6) * 16;

    // per-row sampled bias (register; e = n*NOUT + c)
    float bias;
    {
        int c = c0 + ec;
        float eps = tf_normal(bk0, bk1, (unsigned)(n * NOUT + c));
        bias = fmaf(eps, expf(vb[c]), mub[c]);
    }

    wmma::fragment<wmma::accumulator, 16, 16, 16, float> acc[2];
    wmma::fill_fragment(acc[0], 0.0f);
    wmma::fill_fragment(acc[1], 0.0f);

    const unsigned ebase = (unsigned)(n * NOUT + c0) * (unsigned)K;
    const __nv_bfloat16* bh = Bhi + (size_t)n * bStride;
    const __nv_bfloat16* bl = Blo + (size_t)n * bStride;

    for (int k0 = 0; k0 < K; k0 += KCH) {
        const int buf = (k0 >> 5) & 1;
        // ---- generate + split W chunk: 64c x 32k; 4 row-groups of 16 ----
#pragma unroll 2
        for (int q = 0; q < 4; q++) {
            const int row = rbase + q * 16;
            const size_t goff = (size_t)(c0 + row) * K + k0 + qk;
            float4 m  = *reinterpret_cast<const float4*>(mu + goff);
            float4 sv = *reinterpret_cast<const float4*>(s  + goff);
            float r4[4];
            tf_normal4(wk0, wk1, ebase + (unsigned)(row * K + k0 + qk), r4);
            float w0 = fmaf(r4[0], sv.x, m.x);
            float w1 = fmaf(r4[1], sv.y, m.y);
            float w2 = fmaf(r4[2], sv.z, m.z);
            float w3 = fmaf(r4[3], sv.w, m.w);
            unsigned hp0 = pack_bf16x2(w1, w0);
            unsigned hp1 = pack_bf16x2(w3, w2);
            float h0 = __uint_as_float(hp0 << 16);
            float h1 = __uint_as_float(hp0 & 0xFFFF0000u);
            float h2 = __uint_as_float(hp1 << 16);
            float h3 = __uint_as_float(hp1 & 0xFFFF0000u);
            unsigned lp0 = pack_bf16x2(w1 - h1, w0 - h0);
            unsigned lp1 = pack_bf16x2(w3 - h3, w2 - h2);
            int off = row * WST + qk;
            *reinterpret_cast<uint2*>(&Whi[buf][off]) = make_uint2(hp0, hp1);
            *reinterpret_cast<uint2*>(&Wlo[buf][off]) = make_uint2(lp0, lp1);
        }
        __syncthreads();   // gen(buf) visible; prior chunk's MMA reads done

        // ---- tensor-pipe GEMM on chunk (overlaps with next iter's gen) ----
#pragma unroll
        for (int kk = 0; kk < KCH; kk += 16) {
            wmma::fragment<wmma::matrix_a, 16, 16, 16, __nv_bfloat16, wmma::row_major> ahi, alo;
            wmma::load_matrix_sync(ahi, &Whi[buf][warp * 16 * WST + kk], WST);
            wmma::load_matrix_sync(alo, &Wlo[buf][warp * 16 * WST + kk], WST);
#pragma unroll
            for (int nb = 0; nb < 2; nb++) {
                wmma::fragment<wmma::matrix_b, 16, 16, 16, __nv_bfloat16, wmma::col_major> bhf, blf;
                wmma::load_matrix_sync(bhf, bh + (size_t)(nb * 16) * K + (k0 + kk), K);
                wmma::load_matrix_sync(blf, bl + (size_t)(nb * 16) * K + (k0 + kk), K);
                wmma::mma_sync(acc[nb], ahi, bhf, acc[nb]);
                wmma::mma_sync(acc[nb], ahi, blf, acc[nb]);
                wmma::mma_sync(acc[nb], alo, bhf, acc[nb]);
            }
        }
        // no trailing barrier: next gen writes buf^1; the next __syncthreads
        // guarantees all warps finished reading buf before it is rewritten.
    }

    __syncthreads();
    // ---- D -> smem -> epilogue ----
    wmma::store_matrix_sync(&Dsm[warp * 16 * DST + 0],  acc[0], DST, wmma::mem_row_major);
    wmma::store_matrix_sync(&Dsm[warp * 16 * DST + 16], acc[1], DST, wmma::mem_row_major);
    __syncthreads();

    {
#pragma unroll
        for (int b = eb; b < eb + 16; b++) {
            float v = Dsm[ec * DST + b] + bias;
            if (!LAST) {
                v = fmaxf(v, 0.0f);
                __nv_bfloat16 hi = __float2bfloat16_rn(v);
                __nv_bfloat16 lo = __float2bfloat16_rn(v - __bfloat162float(hi));
                size_t o = ((size_t)n * BATCH + b) * NOUT + (c0 + ec);
                g_Hhi[o] = hi; g_Hlo[o] = lo;
            } else {
                Out[((size_t)n * BATCH + b) * NOUT + (c0 + ec)] = v;
            }
        }
    }
}

// -------------------- host-side threefry for subkey derivation --------------------
static inline unsigned h_rotl(unsigned x, int r) { return (x << r) | (x >> (32 - r)); }
static void h_tf2x32(unsigned k0, unsigned k1, unsigned x0, unsigned x1,
                     unsigned& o0, unsigned& o1)
{
    const unsigned ks2 = k0 ^ k1 ^ 0x1BD11BDAu;
    x0 += k0; x1 += k1;
    static const int R[2][4] = {{13, 15, 26, 6}, {17, 29, 16, 24}};
    const unsigned ks[3] = {k0, k1, ks2};
    for (int g = 0; g < 5; g++) {
        for (int r = 0; r < 4; r++) {
            x0 += x1; x1 = h_rotl(x1, R[g & 1][r]); x1 ^= x0;
        }
        x0 += ks[(g + 1) % 3];
        x1 += ks[(g + 2) % 3] + (unsigned)(g + 1);
    }
    o0 = x0; o1 = x1;
}

extern "C" void kernel_launch(void* const* d_in, const int* in_sizes, int n_in,
                              void* d_out, int out_size)
{
    const float* x    = (const float*)d_in[0];
    const float* muW1 = (const float*)d_in[1];
    const float* mub1 = (const float*)d_in[2];
    const float* muW2 = (const float*)d_in[3];
    const float* mub2 = (const float*)d_in[4];
    const float* vW1  = (const float*)d_in[5];
    const float* vb1  = (const float*)d_in[6];
    const float* vW2  = (const float*)d_in[7];
    const float* vb2  = (const float*)d_in[8];
    float* out = (float*)d_out;

    unsigned keys[4][2];
    for (unsigned i = 0; i < 4; i++)
        h_tf2x32(0u, 42u, 0u, i, keys[i][0], keys[i][1]);

    float *sW1, *sW2;
    __nv_bfloat16 *xhi, *xlo, *Hhi, *Hlo;
    cudaGetSymbolAddress((void**)&sW1, g_sW1);
    cudaGetSymbolAddress((void**)&sW2, g_sW2);
    cudaGetSymbolAddress((void**)&xhi, g_xhi);
    cudaGetSymbolAddress((void**)&xlo, g_xlo);
    cudaGetSymbolAddress((void**)&Hhi, g_Hhi);
    cudaGetSymbolAddress((void**)&Hlo, g_Hlo);

    prep_kernel<<<(DH * DIN + 255) / 256, 256>>>(x, vW1, vW2);

    // layer 1: h = relu(x @ W1^T + b1); 1200 blocks
    fused_wmma<DIN, DH, false><<<dim3(NS, DH / 64), 128>>>(
        muW1, sW1, mub1, vb1, xhi, xlo, nullptr,
        keys[0][0], keys[0][1], keys[1][0], keys[1][1], 0LL);

    // layer 2: y = h @ W2^T + b2; 600 blocks
    fused_wmma<DH, DOUT, true><<<dim3(NS, DOUT / 64), 128>>>(
        muW2, sW2, mub2, vb2, Hhi, Hlo, out,
        keys[2][0], keys[2][1], keys[3][0], keys[3][1],
        (long long)(BATCH * DH));
}